// round 5
// baseline (speedup 1.0000x reference)
#include <cuda_runtime.h>

#define B_  64
#define T_  2048
#define H_  128
#define N3  384
#define BT  (B_ * T_)

typedef unsigned long long ull;

// Scratch (allocation-free rule: __device__ globals). g_gx padded by one row
// so the scan's next-step prefetch can be unconditional.
__device__ float g_gx  [ (size_t)BT * N3 + N3 ];
__device__ float g_buf0[ (size_t)BT * H_ ];
__device__ float g_buf1[ (size_t)BT * H_ ];

// ---------------- packed f32x2 helpers (register-only asm: safe) -----------
__device__ __forceinline__ ull pk2(float lo, float hi) {
    ull r; asm("mov.b64 %0,{%1,%2};" : "=l"(r) : "f"(lo), "f"(hi)); return r;
}
__device__ __forceinline__ ull ffma2(ull a, ull b, ull c) {
    ull d; asm("fma.rn.f32x2 %0,%1,%2,%3;" : "=l"(d) : "l"(a), "l"(b), "l"(c)); return d;
}
__device__ __forceinline__ ull fadd2(ull a, ull b) {
    ull d; asm("add.rn.f32x2 %0,%1,%2;" : "=l"(d) : "l"(a), "l"(b)); return d;
}
__device__ __forceinline__ void unpk2(ull v, float& lo, float& hi) {
    asm("mov.b64 {%0,%1},%2;" : "=f"(lo), "=f"(hi) : "l"(v));
}

#define LOG2E  1.442695040888963f
#define NLOG2E (-1.442695040888963f)
#define N2LOG2E (-2.885390081777927f)

// Branch-free clamped sigmoid: 1/(1+2^(-x*log2e)).  x<<0 -> clamp -> ~1e-38.
__device__ __forceinline__ float fsigmoid(float x) {
    float e = exp2f(fminf(x * NLOG2E, 126.f));
    return __fdividef(1.f, 1.f + e);
}

// ---------------------------------------------------------------------------
// GEMM: C[M,N] = A[M,128] @ Bm[128,N] + bias[N] (optional sigmoid epilogue)
// BM=64, BN=128, BK=32, 256 threads, FFMA2 inner product, ull2 sB reads.
// ---------------------------------------------------------------------------
__global__ void __launch_bounds__(256) gemm_bias(
    const float* __restrict__ A,
    const float* __restrict__ Bm,
    const float* __restrict__ bias,
    float*       __restrict__ C,
    int N, int applySigmoid)
{
    __shared__ float sA[64][33];
    __shared__ __align__(16) float sB[32][128];

    const int m0 = blockIdx.x * 64;
    const int n0 = blockIdx.y * 128;
    const int tid = threadIdx.x;
    const int tx = tid & 15;
    const int ty = tid >> 4;
    const int arow = tid >> 3;
    const int akq  = tid & 7;
    const int brow = tid >> 5;
    const int bcol = tid & 31;

    ull acc2[4][4];
    #pragma unroll
    for (int i = 0; i < 4; i++)
        #pragma unroll
        for (int j = 0; j < 4; j++) acc2[i][j] = 0ULL;

    for (int k0 = 0; k0 < 128; k0 += 32) {
        float4 a0 = *(const float4*)(A + (size_t)(m0 + arow     ) * H_ + k0 + akq * 4);
        float4 a1 = *(const float4*)(A + (size_t)(m0 + arow + 32) * H_ + k0 + akq * 4);
        float4 b0 = *(const float4*)(Bm + (size_t)(k0 + brow     ) * N + n0 + bcol * 4);
        float4 b1 = *(const float4*)(Bm + (size_t)(k0 + brow +  8) * N + n0 + bcol * 4);
        float4 b2 = *(const float4*)(Bm + (size_t)(k0 + brow + 16) * N + n0 + bcol * 4);
        float4 b3 = *(const float4*)(Bm + (size_t)(k0 + brow + 24) * N + n0 + bcol * 4);
        __syncthreads();
        sA[arow     ][akq * 4 + 0] = a0.x;  sA[arow     ][akq * 4 + 1] = a0.y;
        sA[arow     ][akq * 4 + 2] = a0.z;  sA[arow     ][akq * 4 + 3] = a0.w;
        sA[arow + 32][akq * 4 + 0] = a1.x;  sA[arow + 32][akq * 4 + 1] = a1.y;
        sA[arow + 32][akq * 4 + 2] = a1.z;  sA[arow + 32][akq * 4 + 3] = a1.w;
        *(float4*)&sB[brow     ][bcol * 4] = b0;
        *(float4*)&sB[brow +  8][bcol * 4] = b1;
        *(float4*)&sB[brow + 16][bcol * 4] = b2;
        *(float4*)&sB[brow + 24][bcol * 4] = b3;
        __syncthreads();

        #pragma unroll
        for (int k = 0; k < 32; k++) {
            ull pa[4];
            #pragma unroll
            for (int i = 0; i < 4; i++) {
                float a = sA[ty * 4 + i][k];
                pa[i] = pk2(a, a);
            }
            ulonglong2 bv0 = *(const ulonglong2*)&sB[k][tx * 8];
            ulonglong2 bv1 = *(const ulonglong2*)&sB[k][tx * 8 + 4];
            #pragma unroll
            for (int i = 0; i < 4; i++) {
                acc2[i][0] = ffma2(pa[i], bv0.x, acc2[i][0]);
                acc2[i][1] = ffma2(pa[i], bv0.y, acc2[i][1]);
                acc2[i][2] = ffma2(pa[i], bv1.x, acc2[i][2]);
                acc2[i][3] = ffma2(pa[i], bv1.y, acc2[i][3]);
            }
        }
    }

    float bs[8];
    #pragma unroll
    for (int j = 0; j < 8; j++) bs[j] = bias[n0 + tx * 8 + j];

    #pragma unroll
    for (int i = 0; i < 4; i++) {
        const int row = m0 + ty * 4 + i;
        float v[8];
        #pragma unroll
        for (int j = 0; j < 4; j++) unpk2(acc2[i][j], v[2 * j], v[2 * j + 1]);
        #pragma unroll
        for (int j = 0; j < 8; j++) {
            float x = v[j] + bs[j];
            v[j] = applySigmoid ? fsigmoid(x) : x;
        }
        float4 o0 = {v[0], v[1], v[2], v[3]};
        float4 o1 = {v[4], v[5], v[6], v[7]};
        *(float4*)(C + (size_t)row * N + n0 + tx * 8    ) = o0;
        *(float4*)(C + (size_t)row * N + n0 + tx * 8 + 4) = o1;
    }
}

// ---------------------------------------------------------------------------
// GRU scan: one CTA per batch, 384 threads. Thread t owns rec column t as
// 64 packed f32x2 regs. h_s read as ulonglong2 (no packing MOVs).
// Role 2 precomputes its tanh-argument terms and h_old BEFORE the barrier;
// the inter-barrier chain is FFMA->FMNMX->EX2->FADD->RCP->FFMA->FFMA (~65cyc).
// ---------------------------------------------------------------------------
__global__ void __launch_bounds__(384, 1) gru_scan(
    const float* __restrict__ gx,     // [B, T, 384] = x@kernel + bias_in
    const float* __restrict__ rec,    // [128, 384]
    const float* __restrict__ brec_g, // [384]
    float*       __restrict__ y)      // [B, T, 128]
{
    const int b = blockIdx.x;
    const int t = threadIdx.x;
    const int role = t >> 7;          // 0=z, 1=r, 2=h
    const int i    = t & 127;

    ull w2[64];
    #pragma unroll
    for (int j = 0; j < 64; j++)
        w2[j] = pk2(rec[(2 * j) * N3 + t], rec[(2 * j + 1) * N3 + t]);
    const float brec = brec_g[t];

    __shared__ __align__(16) float h_s[H_];
    __shared__ float sz[H_];
    __shared__ float sr[H_];
    if (t < H_) h_s[t] = 0.f;
    __syncthreads();

    const ulonglong2* __restrict__ hp = (const ulonglong2*)h_s;
    const float* gxp = gx + (size_t)b * T_ * N3 + t;
    float*       yp  = y  + (size_t)b * T_ * H_ + i;

    float gxv = __ldg(gxp);           // step 0, prefetched

    for (int step = 0; step < T_; ++step) {
        // prefetch next step's gx (g_gx padded -> always safe)
        float gxn = __ldg(gxp + (size_t)(step + 1) * N3);

        // gh[t] = sum_k h[k] * rec[k][t]  -- ull2 loads feed FFMA2 directly
        ull a0 = 0ULL, a1 = 0ULL, a2 = 0ULL, a3 = 0ULL;
        #pragma unroll
        for (int q = 0; q < 32; q += 2) {
            ulonglong2 hA = hp[q];
            ulonglong2 hB = hp[q + 1];
            a0 = ffma2(hA.x, w2[2 * q + 0], a0);
            a1 = ffma2(hA.y, w2[2 * q + 1], a1);
            a2 = ffma2(hB.x, w2[2 * q + 2], a2);
            a3 = ffma2(hB.y, w2[2 * q + 3], a3);
        }
        a0 = fadd2(fadd2(a0, a1), fadd2(a2, a3));
        float lo, hi;
        unpk2(a0, lo, hi);
        const float gh = lo + hi + brec;   // == hz (role 0) / hr (1) / hh (2)

        float p = 0.f, hh2 = 0.f, hold = 0.f;
        if (role == 0)      sz[i] = fsigmoid(gxv + gh);
        else if (role == 1) sr[i] = fsigmoid(gxv + gh);
        else {
            p    = gxv * N2LOG2E;     // -2*log2e * xh
            hh2  = gh  * N2LOG2E;     // -2*log2e * hh
            hold = h_s[i];            // h(t-1), read before barrier
        }
        __syncthreads();

        if (role == 2) {
            float r   = sr[i];
            float z   = sz[i];
            float arg = fminf(fmaf(r, hh2, p), 126.f);   // -2log2e*(xh+r*hh)
            float e   = exp2f(arg);
            float c   = __fdividef(2.f, 1.f + e) - 1.f;  // tanh
            float hn  = fmaf(z, hold - c, c);            // z*h + (1-z)*c
            h_s[i] = hn;
            yp[(size_t)step * H_] = hn;
        }
        __syncthreads();   // h_s update visible before next dot

        gxv = gxn;
    }
}

// ---------------------------------------------------------------------------
extern "C" void kernel_launch(void* const* d_in, const int* in_sizes, int n_in,
                              void* d_out, int out_size)
{
    const float* X     = (const float*)d_in[0];
    const float* kern  = (const float*)d_in[1];
    const float* rec   = (const float*)d_in[2];
    const float* b_in  = (const float*)d_in[3];
    const float* b_rec = (const float*)d_in[4];
    const float* W_out = (const float*)d_in[5];
    const float* b_out = (const float*)d_in[6];
    float* out = (float*)d_out;

    float *gxs, *buf0, *buf1;
    cudaGetSymbolAddress((void**)&gxs,  g_gx);
    cudaGetSymbolAddress((void**)&buf0, g_buf0);
    cudaGetSymbolAddress((void**)&buf1, g_buf1);

    dim3 gg(BT / 64, N3 / 128);   // (2048, 3)
    dim3 gf(BT / 64, 1);

    gemm_bias<<<gg, 256>>>(X,    kern, b_in, gxs, N3, 0);
    gru_scan <<<B_, 384>>>(gxs, rec, b_rec, buf0);

    gemm_bias<<<gg, 256>>>(buf0, kern, b_in, gxs, N3, 0);
    gru_scan <<<B_, 384>>>(gxs, rec, b_rec, buf1);

    gemm_bias<<<gg, 256>>>(buf1, kern, b_in, gxs, N3, 0);
    gru_scan <<<B_, 384>>>(gxs, rec, b_rec, buf0);

    gemm_bias<<<gf, 256>>>(buf0, W_out, b_out, out, H_, 1);
}

// round 6
// speedup vs baseline: 1.5423x; 1.5423x over previous
#include <cuda_runtime.h>

#define B_  64
#define T_  2048
#define H_  128
#define N3  384
#define BT  (B_ * T_)

typedef unsigned long long ull;

// Scratch (allocation-free rule: __device__ globals). g_gx padded by one row
// so the scan's next-step prefetch can be unconditional.
__device__ float g_gx  [ (size_t)BT * N3 + N3 ];
__device__ float g_buf0[ (size_t)BT * H_ ];
__device__ float g_buf1[ (size_t)BT * H_ ];

// ---------------- packed f32x2 helpers (register-only asm: safe) -----------
__device__ __forceinline__ ull pk2(float lo, float hi) {
    ull r; asm("mov.b64 %0,{%1,%2};" : "=l"(r) : "f"(lo), "f"(hi)); return r;
}
__device__ __forceinline__ ull ffma2(ull a, ull b, ull c) {
    ull d; asm("fma.rn.f32x2 %0,%1,%2,%3;" : "=l"(d) : "l"(a), "l"(b), "l"(c)); return d;
}
__device__ __forceinline__ ull fadd2(ull a, ull b) {
    ull d; asm("add.rn.f32x2 %0,%1,%2;" : "=l"(d) : "l"(a), "l"(b)); return d;
}
__device__ __forceinline__ void unpk2(ull v, float& lo, float& hi) {
    asm("mov.b64 {%0,%1},%2;" : "=f"(lo), "=f"(hi) : "l"(v));
}
__device__ __forceinline__ unsigned smem_u32(const void* p) {
    unsigned a;
    asm("{.reg .u64 u; cvta.to.shared.u64 u,%1; cvt.u32.u64 %0,u;}" : "=r"(a) : "l"(p));
    return a;
}
// Volatile shared load: explicit shared space (fast LDS.128 path) AND
// ordering-safe (volatile cannot be hoisted/CSE'd across __syncthreads).
__device__ __forceinline__ void lds_v2u64(unsigned addr, ull& a, ull& b) {
    asm volatile("ld.shared.v2.u64 {%0,%1},[%2];" : "=l"(a), "=l"(b) : "r"(addr));
}

#define NLOG2E  (-1.442695040888963f)
#define N2LOG2E (-2.885390081777927f)

// Branch-free clamped sigmoid: 1/(1+2^(-x*log2e)).
__device__ __forceinline__ float fsigmoid(float x) {
    float e = exp2f(fminf(x * NLOG2E, 126.f));
    return __fdividef(1.f, 1.f + e);
}

// ---------------------------------------------------------------------------
// GEMM: C[M,N] = A[M,128] @ Bm[128,N] + bias[N] (optional sigmoid epilogue)
// BM=64, BN=128, BK=32, 256 threads, FFMA2 inner product.
// sB read via volatile ld.shared.v2.u64 (packed pairs, no MOVs).
// ---------------------------------------------------------------------------
__global__ void __launch_bounds__(256) gemm_bias(
    const float* __restrict__ A,
    const float* __restrict__ Bm,
    const float* __restrict__ bias,
    float*       __restrict__ C,
    int N, int applySigmoid)
{
    __shared__ float sA[64][33];
    __shared__ __align__(16) float sB[32][128];

    const int m0 = blockIdx.x * 64;
    const int n0 = blockIdx.y * 128;
    const int tid = threadIdx.x;
    const int tx = tid & 15;
    const int ty = tid >> 4;
    const int arow = tid >> 3;
    const int akq  = tid & 7;
    const int brow = tid >> 5;
    const int bcol = tid & 31;

    const unsigned sb_base = smem_u32(&sB[0][0]) + tx * 32;  // tx*8 floats

    ull acc2[4][4];
    #pragma unroll
    for (int i = 0; i < 4; i++)
        #pragma unroll
        for (int j = 0; j < 4; j++) acc2[i][j] = 0ULL;

    for (int k0 = 0; k0 < 128; k0 += 32) {
        float4 a0 = *(const float4*)(A + (size_t)(m0 + arow     ) * H_ + k0 + akq * 4);
        float4 a1 = *(const float4*)(A + (size_t)(m0 + arow + 32) * H_ + k0 + akq * 4);
        float4 b0 = *(const float4*)(Bm + (size_t)(k0 + brow     ) * N + n0 + bcol * 4);
        float4 b1 = *(const float4*)(Bm + (size_t)(k0 + brow +  8) * N + n0 + bcol * 4);
        float4 b2 = *(const float4*)(Bm + (size_t)(k0 + brow + 16) * N + n0 + bcol * 4);
        float4 b3 = *(const float4*)(Bm + (size_t)(k0 + brow + 24) * N + n0 + bcol * 4);
        __syncthreads();
        sA[arow     ][akq * 4 + 0] = a0.x;  sA[arow     ][akq * 4 + 1] = a0.y;
        sA[arow     ][akq * 4 + 2] = a0.z;  sA[arow     ][akq * 4 + 3] = a0.w;
        sA[arow + 32][akq * 4 + 0] = a1.x;  sA[arow + 32][akq * 4 + 1] = a1.y;
        sA[arow + 32][akq * 4 + 2] = a1.z;  sA[arow + 32][akq * 4 + 3] = a1.w;
        *(float4*)&sB[brow     ][bcol * 4] = b0;
        *(float4*)&sB[brow +  8][bcol * 4] = b1;
        *(float4*)&sB[brow + 16][bcol * 4] = b2;
        *(float4*)&sB[brow + 24][bcol * 4] = b3;
        __syncthreads();

        #pragma unroll
        for (int k = 0; k < 32; k++) {
            ull pa[4];
            #pragma unroll
            for (int i = 0; i < 4; i++) {
                float a = sA[ty * 4 + i][k];
                pa[i] = pk2(a, a);
            }
            ull b01, b23, b45, b67;
            lds_v2u64(sb_base + k * 512,      b01, b23);
            lds_v2u64(sb_base + k * 512 + 16, b45, b67);
            #pragma unroll
            for (int i = 0; i < 4; i++) {
                acc2[i][0] = ffma2(pa[i], b01, acc2[i][0]);
                acc2[i][1] = ffma2(pa[i], b23, acc2[i][1]);
                acc2[i][2] = ffma2(pa[i], b45, acc2[i][2]);
                acc2[i][3] = ffma2(pa[i], b67, acc2[i][3]);
            }
        }
    }

    float bs[8];
    #pragma unroll
    for (int j = 0; j < 8; j++) bs[j] = bias[n0 + tx * 8 + j];

    #pragma unroll
    for (int i = 0; i < 4; i++) {
        const int row = m0 + ty * 4 + i;
        float v[8];
        #pragma unroll
        for (int j = 0; j < 4; j++) unpk2(acc2[i][j], v[2 * j], v[2 * j + 1]);
        #pragma unroll
        for (int j = 0; j < 8; j++) {
            float x = v[j] + bs[j];
            v[j] = applySigmoid ? fsigmoid(x) : x;
        }
        float4 o0 = {v[0], v[1], v[2], v[3]};
        float4 o1 = {v[4], v[5], v[6], v[7]};
        *(float4*)(C + (size_t)row * N + n0 + tx * 8    ) = o0;
        *(float4*)(C + (size_t)row * N + n0 + tx * 8 + 4) = o1;
    }
}

// ---------------------------------------------------------------------------
// GRU scan: one CTA per batch, 384 threads. Thread t owns rec column t as
// 64 packed f32x2 regs. h_s read via volatile ld.shared.v2.u64: packed pairs
// land directly in FFMA2 operands (zero packing MOVs), explicit shared path,
// barrier-safe. Role 2 precomputes its tanh terms + h_old before the barrier.
// ---------------------------------------------------------------------------
__global__ void __launch_bounds__(384, 1) gru_scan(
    const float* __restrict__ gx,     // [B, T, 384] = x@kernel + bias_in
    const float* __restrict__ rec,    // [128, 384]
    const float* __restrict__ brec_g, // [384]
    float*       __restrict__ y)      // [B, T, 128]
{
    const int b = blockIdx.x;
    const int t = threadIdx.x;
    const int role = t >> 7;          // 0=z, 1=r, 2=h
    const int i    = t & 127;

    ull w2[64];
    #pragma unroll
    for (int j = 0; j < 64; j++)
        w2[j] = pk2(rec[(2 * j) * N3 + t], rec[(2 * j + 1) * N3 + t]);
    const float brec = brec_g[t];

    __shared__ __align__(16) float h_s[H_];
    __shared__ float sz[H_];
    __shared__ float sr[H_];
    if (t < H_) h_s[t] = 0.f;
    __syncthreads();

    const unsigned haddr = smem_u32(h_s);
    const float* gxp = gx + (size_t)b * T_ * N3 + t;
    float*       yp  = y  + (size_t)b * T_ * H_ + i;

    float gxv = __ldg(gxp);           // step 0, prefetched

    for (int step = 0; step < T_; ++step) {
        // prefetch next step's gx (g_gx padded -> always safe)
        float gxn = __ldg(gxp + (size_t)(step + 1) * N3);

        // gh[t] = sum_k h[k] * rec[k][t] -- LDS.128 pairs feed FFMA2 directly
        ull a0 = 0ULL, a1 = 0ULL, a2 = 0ULL, a3 = 0ULL;
        #pragma unroll
        for (int q = 0; q < 8; q++) {
            ull hA0, hA1, hA2, hA3, hB0, hB1, hB2, hB3;
            const unsigned addr = haddr + q * 64;
            lds_v2u64(addr,      hA0, hA1);
            lds_v2u64(addr + 16, hA2, hA3);
            lds_v2u64(addr + 32, hB0, hB1);
            lds_v2u64(addr + 48, hB2, hB3);
            a0 = ffma2(hA0, w2[8 * q + 0], a0);
            a1 = ffma2(hA1, w2[8 * q + 1], a1);
            a2 = ffma2(hA2, w2[8 * q + 2], a2);
            a3 = ffma2(hA3, w2[8 * q + 3], a3);
            a0 = ffma2(hB0, w2[8 * q + 4], a0);
            a1 = ffma2(hB1, w2[8 * q + 5], a1);
            a2 = ffma2(hB2, w2[8 * q + 6], a2);
            a3 = ffma2(hB3, w2[8 * q + 7], a3);
        }
        a0 = fadd2(fadd2(a0, a1), fadd2(a2, a3));
        float lo, hi;
        unpk2(a0, lo, hi);
        const float gh = lo + hi + brec;   // == hz (role 0) / hr (1) / hh (2)

        float p = 0.f, hh2 = 0.f, hold = 0.f;
        if (role == 0)      sz[i] = fsigmoid(gxv + gh);
        else if (role == 1) sr[i] = fsigmoid(gxv + gh);
        else {
            p    = gxv * N2LOG2E;     // -2*log2e * xh
            hh2  = gh  * N2LOG2E;     // -2*log2e * hh
            hold = h_s[i];            // h(t-1), read before barrier
        }
        __syncthreads();

        if (role == 2) {
            float r   = sr[i];
            float z   = sz[i];
            float arg = fminf(fmaf(r, hh2, p), 126.f);   // -2log2e*(xh+r*hh)
            float e   = exp2f(arg);
            float c   = __fdividef(2.f, 1.f + e) - 1.f;  // tanh
            float hn  = fmaf(z, hold - c, c);            // z*h + (1-z)*c
            h_s[i] = hn;
            yp[(size_t)step * H_] = hn;
        }
        __syncthreads();   // h_s update visible before next dot

        gxv = gxn;
    }
}

// ---------------------------------------------------------------------------
extern "C" void kernel_launch(void* const* d_in, const int* in_sizes, int n_in,
                              void* d_out, int out_size)
{
    const float* X     = (const float*)d_in[0];
    const float* kern  = (const float*)d_in[1];
    const float* rec   = (const float*)d_in[2];
    const float* b_in  = (const float*)d_in[3];
    const float* b_rec = (const float*)d_in[4];
    const float* W_out = (const float*)d_in[5];
    const float* b_out = (const float*)d_in[6];
    float* out = (float*)d_out;

    float *gxs, *buf0, *buf1;
    cudaGetSymbolAddress((void**)&gxs,  g_gx);
    cudaGetSymbolAddress((void**)&buf0, g_buf0);
    cudaGetSymbolAddress((void**)&buf1, g_buf1);

    dim3 gg(BT / 64, N3 / 128);   // (2048, 3)
    dim3 gf(BT / 64, 1);

    gemm_bias<<<gg, 256>>>(X,    kern, b_in, gxs, N3, 0);
    gru_scan <<<B_, 384>>>(gxs, rec, b_rec, buf0);

    gemm_bias<<<gg, 256>>>(buf0, kern, b_in, gxs, N3, 0);
    gru_scan <<<B_, 384>>>(gxs, rec, b_rec, buf1);

    gemm_bias<<<gg, 256>>>(buf1, kern, b_in, gxs, N3, 0);
    gru_scan <<<B_, 384>>>(gxs, rec, b_rec, buf0);

    gemm_bias<<<gf, 256>>>(buf0, W_out, b_out, out, H_, 1);
}

// round 8
// speedup vs baseline: 2.0128x; 1.3051x over previous
#include <cuda_runtime.h>

#define B_  64
#define T_  2048
#define H_  128
#define N3  384
#define BT  (B_ * T_)
#define CHUNK   64
#define NCHUNK  (T_ / CHUNK)        // 32
#define SCAN_CTAS 64
#define GEMM_CTAS 84
#define GRID      (SCAN_CTAS + GEMM_CTAS)   // 148 = 1 CTA/SM, all resident

typedef unsigned long long ull;

// Scratch (allocation-free rule). g_gx padded one row for unconditional prefetch.
__device__ float g_gx  [(size_t)BT * N3 + N3];
__device__ float g_bufA[(size_t)BT * H_];
__device__ float g_bufB[(size_t)BT * H_];
// Flags: gx chunk counters (target 3 = n-tiles) and scan chunk-done flags.
__device__ int g_cnt_gx [3][B_][NCHUNK];
__device__ int g_rdy_scan[3][B_][NCHUNK];

// ---------------- packed f32x2 helpers (register-only asm: safe) -----------
__device__ __forceinline__ ull pk2(float lo, float hi) {
    ull r; asm("mov.b64 %0,{%1,%2};" : "=l"(r) : "f"(lo), "f"(hi)); return r;
}
__device__ __forceinline__ ull ffma2(ull a, ull b, ull c) {
    ull d; asm("fma.rn.f32x2 %0,%1,%2,%3;" : "=l"(d) : "l"(a), "l"(b), "l"(c)); return d;
}
__device__ __forceinline__ ull fadd2(ull a, ull b) {
    ull d; asm("add.rn.f32x2 %0,%1,%2;" : "=l"(d) : "l"(a), "l"(b)); return d;
}
__device__ __forceinline__ void unpk2(ull v, float& lo, float& hi) {
    asm("mov.b64 {%0,%1},%2;" : "=f"(lo), "=f"(hi) : "l"(v));
}
__device__ __forceinline__ unsigned smem_u32(const void* p) {
    unsigned a;
    asm("{.reg .u64 u; cvta.to.shared.u64 u,%1; cvt.u32.u64 %0,u;}" : "=r"(a) : "l"(p));
    return a;
}
// Volatile shared load: fast explicit-shared LDS.128, barrier-safe.
__device__ __forceinline__ void lds_v2u64(unsigned addr, ull& a, ull& b) {
    asm volatile("ld.shared.v2.u64 {%0,%1},[%2];" : "=l"(a), "=l"(b) : "r"(addr));
}
// Coherent L2 loads for intra-kernel-produced data (never stale: .cg skips L1).
__device__ __forceinline__ float ldg_cg(const float* p) {
    float v; asm volatile("ld.global.cg.f32 %0,[%1];" : "=f"(v) : "l"(p)); return v;
}
__device__ __forceinline__ float4 ldg_cg4(const float* p) {
    float4 v;
    asm volatile("ld.global.cg.v4.f32 {%0,%1,%2,%3},[%4];"
                 : "=f"(v.x), "=f"(v.y), "=f"(v.z), "=f"(v.w) : "l"(p));
    return v;
}
// Acquire/release flag ops
__device__ __forceinline__ int ld_acq(const int* p) {
    int v; asm volatile("ld.acquire.gpu.global.b32 %0,[%1];" : "=r"(v) : "l"(p)); return v;
}
__device__ __forceinline__ void st_rel(int* p, int v) {
    asm volatile("st.release.gpu.global.b32 [%0],%1;" :: "l"(p), "r"(v) : "memory");
}
__device__ __forceinline__ void red_rel_add1(int* p) {
    asm volatile("red.release.gpu.global.add.s32 [%0],%1;" :: "l"(p), "r"(1) : "memory");
}

#define NLOG2E  (-1.442695040888963f)
#define N2LOG2E (-2.885390081777927f)

__device__ __forceinline__ float fsigmoid(float x) {
    float e = exp2f(fminf(x * NLOG2E, 126.f));
    return __fdividef(1.f, 1.f + e);
}

// ---------------------------------------------------------------------------
// GEMM tile: C[m0:m0+64, n0:n0+128] = A[m0:,0:128] @ Bm[:, n0:] + bias
// All 384 threads enter (barriers uniform); tid<256 do the work.
// A loaded via ld.global.cg (may be produced within this kernel).
// ---------------------------------------------------------------------------
__device__ void gemm_tile(
    const float* A, const float* __restrict__ Bm,
    const float* __restrict__ bias, float* __restrict__ C,
    int N, int m0, int n0, int applySigmoid,
    float (*sA)[33], float (*sB)[128])
{
    const int tid = threadIdx.x;
    const bool act = tid < 256;
    const int tx = tid & 15;
    const int ty = (tid >> 4) & 15;
    const int arow = (tid >> 3) & 31;
    const int akq  = tid & 7;
    const int brow = (tid >> 5) & 7;
    const int bcol = tid & 31;
    const unsigned sb_base = smem_u32(&sB[0][0]) + tx * 32;

    ull acc2[4][4];
    #pragma unroll
    for (int i = 0; i < 4; i++)
        #pragma unroll
        for (int j = 0; j < 4; j++) acc2[i][j] = 0ULL;

    for (int k0 = 0; k0 < 128; k0 += 32) {
        float4 a0, a1, b0, b1, b2, b3;
        if (act) {
            a0 = ldg_cg4(A + (size_t)(m0 + arow     ) * H_ + k0 + akq * 4);
            a1 = ldg_cg4(A + (size_t)(m0 + arow + 32) * H_ + k0 + akq * 4);
            b0 = *(const float4*)(Bm + (size_t)(k0 + brow     ) * N + n0 + bcol * 4);
            b1 = *(const float4*)(Bm + (size_t)(k0 + brow +  8) * N + n0 + bcol * 4);
            b2 = *(const float4*)(Bm + (size_t)(k0 + brow + 16) * N + n0 + bcol * 4);
            b3 = *(const float4*)(Bm + (size_t)(k0 + brow + 24) * N + n0 + bcol * 4);
        }
        __syncthreads();
        if (act) {
            sA[arow     ][akq * 4 + 0] = a0.x;  sA[arow     ][akq * 4 + 1] = a0.y;
            sA[arow     ][akq * 4 + 2] = a0.z;  sA[arow     ][akq * 4 + 3] = a0.w;
            sA[arow + 32][akq * 4 + 0] = a1.x;  sA[arow + 32][akq * 4 + 1] = a1.y;
            sA[arow + 32][akq * 4 + 2] = a1.z;  sA[arow + 32][akq * 4 + 3] = a1.w;
            *(float4*)&sB[brow     ][bcol * 4] = b0;
            *(float4*)&sB[brow +  8][bcol * 4] = b1;
            *(float4*)&sB[brow + 16][bcol * 4] = b2;
            *(float4*)&sB[brow + 24][bcol * 4] = b3;
        }
        __syncthreads();
        if (act) {
            #pragma unroll
            for (int k = 0; k < 32; k++) {
                ull pa[4];
                #pragma unroll
                for (int i = 0; i < 4; i++) {
                    float a = sA[ty * 4 + i][k];
                    pa[i] = pk2(a, a);
                }
                ull b01, b23, b45, b67;
                lds_v2u64(sb_base + k * 512,      b01, b23);
                lds_v2u64(sb_base + k * 512 + 16, b45, b67);
                #pragma unroll
                for (int i = 0; i < 4; i++) {
                    acc2[i][0] = ffma2(pa[i], b01, acc2[i][0]);
                    acc2[i][1] = ffma2(pa[i], b23, acc2[i][1]);
                    acc2[i][2] = ffma2(pa[i], b45, acc2[i][2]);
                    acc2[i][3] = ffma2(pa[i], b67, acc2[i][3]);
                }
            }
        }
    }

    if (act) {
        float bs[8];
        #pragma unroll
        for (int j = 0; j < 8; j++) bs[j] = bias[n0 + tx * 8 + j];
        #pragma unroll
        for (int i = 0; i < 4; i++) {
            const int row = m0 + ty * 4 + i;
            float v[8];
            #pragma unroll
            for (int j = 0; j < 4; j++) unpk2(acc2[i][j], v[2 * j], v[2 * j + 1]);
            #pragma unroll
            for (int j = 0; j < 8; j++) {
                float x = v[j] + bs[j];
                v[j] = applySigmoid ? fsigmoid(x) : x;
            }
            float4 o0 = {v[0], v[1], v[2], v[3]};
            float4 o1 = {v[4], v[5], v[6], v[7]};
            *(float4*)(C + (size_t)row * N + n0 + tx * 8    ) = o0;
            *(float4*)(C + (size_t)row * N + n0 + tx * 8 + 4) = o1;
        }
    }
}

__device__ __forceinline__ void wait_flag(const int* p, int target) {
    if (threadIdx.x == 0) {
        while (ld_acq(p) < target) __nanosleep(128);
    }
    __syncthreads();
}

__global__ void init_flags() {
    const int n = 3 * B_ * NCHUNK;
    int* a = &g_cnt_gx[0][0][0];
    int* b = &g_rdy_scan[0][0][0];
    for (int i = threadIdx.x; i < n; i += blockDim.x) { a[i] = 0; b[i] = 0; }
}

// ---------------------------------------------------------------------------
// Mega-kernel: 64 scan CTAs + 84 GEMM-worker CTAs, all resident (1/SM).
// ---------------------------------------------------------------------------
__global__ void __launch_bounds__(384, 1) mega(
    const float* __restrict__ X,
    const float* __restrict__ kern,
    const float* __restrict__ rec,
    const float* __restrict__ b_in,
    const float* __restrict__ b_rec,
    const float* __restrict__ W_out,
    const float* __restrict__ b_out,
    float*       __restrict__ out)
{
    __shared__ __align__(16) float h_s[H_];
    __shared__ float sz[H_];
    __shared__ float sr[H_];
    __shared__ float sA[64][33];
    __shared__ __align__(16) float sB[32][128];

    const int cta = blockIdx.x;
    const int t   = threadIdx.x;

    if (cta < SCAN_CTAS) {
        // ================= scan worker: batch b, 3 layers sequential =======
        const int b    = cta;
        const int role = t >> 7;
        const int i    = t & 127;

        ull w2[64];
        #pragma unroll
        for (int j = 0; j < 64; j++)
            w2[j] = pk2(rec[(2 * j) * N3 + t], rec[(2 * j + 1) * N3 + t]);
        const float brec = b_rec[t];
        const unsigned haddr = smem_u32(h_s);

        for (int l = 0; l < 3; l++) {
            float* ybase = (l == 1) ? g_bufB : g_bufA;   // l0->A, l1->B, l2->A
            const float* gxp = g_gx + (size_t)b * T_ * N3 + t;
            float*       yp  = ybase + (size_t)b * T_ * H_ + i;

            if (t < H_) h_s[t] = 0.f;
            if (t == 0) {   // chunks 0 and 1 must be ready before first loads
                while (ld_acq(&g_cnt_gx[l][b][0]) < 3) __nanosleep(128);
                while (ld_acq(&g_cnt_gx[l][b][1]) < 3) __nanosleep(128);
            }
            __syncthreads();

            float gxv = ldg_cg(gxp);

            for (int step = 0; step < T_; ++step) {
                if ((step & 63) == 0 && step) {
                    const int c  = step >> 6;
                    const int c2 = (c + 1 < NCHUNK) ? c + 1 : NCHUNK - 1;
                    if (t == 0) {
                        while (ld_acq(&g_cnt_gx[l][b][c ]) < 3) __nanosleep(128);
                        while (ld_acq(&g_cnt_gx[l][b][c2]) < 3) __nanosleep(128);
                    }
                    __syncthreads();
                }

                float gxn = ldg_cg(gxp + (size_t)(step + 1) * N3);

                ull a0 = 0ULL, a1 = 0ULL, a2 = 0ULL, a3 = 0ULL;
                #pragma unroll
                for (int q = 0; q < 8; q++) {
                    ull hA0, hA1, hA2, hA3, hB0, hB1, hB2, hB3;
                    const unsigned addr = haddr + q * 64;
                    lds_v2u64(addr,      hA0, hA1);
                    lds_v2u64(addr + 16, hA2, hA3);
                    lds_v2u64(addr + 32, hB0, hB1);
                    lds_v2u64(addr + 48, hB2, hB3);
                    a0 = ffma2(hA0, w2[8 * q + 0], a0);
                    a1 = ffma2(hA1, w2[8 * q + 1], a1);
                    a2 = ffma2(hA2, w2[8 * q + 2], a2);
                    a3 = ffma2(hA3, w2[8 * q + 3], a3);
                    a0 = ffma2(hB0, w2[8 * q + 4], a0);
                    a1 = ffma2(hB1, w2[8 * q + 5], a1);
                    a2 = ffma2(hB2, w2[8 * q + 6], a2);
                    a3 = ffma2(hB3, w2[8 * q + 7], a3);
                }
                a0 = fadd2(fadd2(a0, a1), fadd2(a2, a3));
                float lo, hi;
                unpk2(a0, lo, hi);
                const float gh = lo + hi + brec;

                float p = 0.f, hh2 = 0.f, hold = 0.f;
                if (role == 0)      sz[i] = fsigmoid(gxv + gh);
                else if (role == 1) sr[i] = fsigmoid(gxv + gh);
                else {
                    p    = gxv * N2LOG2E;
                    hh2  = gh  * N2LOG2E;
                    hold = h_s[i];
                }
                __syncthreads();

                if (role == 2) {
                    float r   = sr[i];
                    float z   = sz[i];
                    float arg = fminf(fmaf(r, hh2, p), 126.f);
                    float e   = exp2f(arg);
                    float c   = __fdividef(2.f, 1.f + e) - 1.f;
                    float hn  = fmaf(z, hold - c, c);
                    h_s[i] = hn;
                    yp[(size_t)step * H_] = hn;
                }
                __syncthreads();

                if ((step & 63) == 63) {   // publish chunk for downstream GEMM
                    if (role == 2) __threadfence();
                    __syncthreads();
                    if (t == 0) st_rel(&g_rdy_scan[l][b][step >> 6], 1);
                }
                gxv = gxn;
            }
        }
    } else {
        // ================= GEMM worker =====================================
        const int wrk = cta - SCAN_CTAS;

        // Phases A/B/C: gx for layers 0/1/2 (chunk-major production order)
        for (int l = 0; l < 3; l++) {
            const float* Asrc = (l == 0) ? X : ((l == 1) ? g_bufA : g_bufB);
            for (int idx = wrk; idx < NCHUNK * B_ * 3; idx += GEMM_CTAS) {
                const int c = idx / (B_ * 3);
                const int r = idx % (B_ * 3);
                const int b = r / 3;
                const int n = r % 3;
                if (l > 0) wait_flag(&g_rdy_scan[l - 1][b][c], 1);
                gemm_tile(Asrc, kern, b_in, g_gx, N3,
                          b * T_ + c * CHUNK, n * 128, 0, sA, sB);
                __threadfence();
                __syncthreads();
                if (t == 0) red_rel_add1(&g_cnt_gx[l][b][c]);
            }
        }
        // Phase D: final projection + sigmoid (input = scan layer-2 out = bufA)
        for (int idx = wrk; idx < NCHUNK * B_; idx += GEMM_CTAS) {
            const int c = idx / B_;
            const int b = idx % B_;
            wait_flag(&g_rdy_scan[2][b][c], 1);
            gemm_tile(g_bufA, W_out, b_out, out, H_,
                      b * T_ + c * CHUNK, 0, 1, sA, sB);
        }
    }
}

// ---------------------------------------------------------------------------
extern "C" void kernel_launch(void* const* d_in, const int* in_sizes, int n_in,
                              void* d_out, int out_size)
{
    const float* X     = (const float*)d_in[0];
    const float* kern  = (const float*)d_in[1];
    const float* rec   = (const float*)d_in[2];
    const float* b_in  = (const float*)d_in[3];
    const float* b_rec = (const float*)d_in[4];
    const float* W_out = (const float*)d_in[5];
    const float* b_out = (const float*)d_in[6];
    float* out = (float*)d_out;

    init_flags<<<1, 256>>>();
    mega<<<GRID, 384>>>(X, kern, rec, b_in, b_rec, W_out, b_out, out);
}